// round 13
// baseline (speedup 1.0000x reference)
#include <cuda_runtime.h>
#include <cuda_bf16.h>
#include <cstdint>

// Problem constants (fixed shapes)
constexpr int DIN      = 1024;   // input dim
constexpr int L        = 65;     // NUM_FREQ + 1
constexpr int N1       = 130;    // 2L (GEMM1 output cols)
constexpr int F        = 64;     // NUM_FREQ
constexpr int K2       = 128;    // 2F (GEMM2 reduction)
constexpr int D        = 512;    // DIM_OUTPUT
constexpr int ROWS_MAX = 65536;  // 16 * 4096

// GEMM1 mma tiling: M=32 per CTA; 8 warps = 2 row-slices x 4 ntile-groups
constexpr int NTILES  = 17;            // 136 cols / 8
constexpr int KSTEPS  = 64;            // 1024 / 16, one kstep per pipeline stage
constexpr int KSTEP_U32 = 2 * NTILES * 32 * 2;       // 2176 u32 = 8704 B per kstep (B frags)
constexpr int M_CTA   = 32;

// gemm1 pipeline: 4-buffer ring, 1 kstep per stage
constexpr int G1_BST   = 8704;             // B bytes per stage
constexpr int G1_XROWB = 96;               // X smem row stride (2-way conflicts max)
constexpr int G1_XST   = M_CTA * G1_XROWB; // 3072 B per stage
constexpr int G1_STAGE = G1_BST + G1_XST;  // 11776
constexpr int G1_BCH   = G1_BST / 16;      // 544 16B chunks
constexpr int G1_XDATA = M_CTA * 4;        // 128 chunks (4 x 16B per row)
constexpr int G1_CHUNKS = G1_BCH + G1_XDATA;   // 672

// GEMM2 mma tiling: per CTA 128 rows x 128 cols, K=128 (8 ksteps), 16 ntiles
constexpr int G2_NT   = 16;
constexpr int G2_KS   = 8;
constexpr int TFRAG_U32_PER_NT = G2_KS * 2 * 32 * 2;     // 1024 u32 per (global) ntile
constexpr int TFRAG_U32 = 64 * TFRAG_U32_PER_NT;         // 65536 u32 = 256 KB total
constexpr int SM2_U32  = G2_NT * TFRAG_U32_PER_NT;       // 16384 u32 = 64 KB per CTA
constexpr int SM2_BYTES = SM2_U32 * 4;

// Scratch (static device globals — no runtime allocation)
__device__ __align__(16) __nv_bfloat16 g_coefh[(size_t)ROWS_MAX * K2];
__device__ __align__(16) __nv_bfloat16 g_coefl[(size_t)ROWS_MAX * K2];
__device__ float g_CS[F];
__device__ float g_SS[F];
__device__ float g_invS[ROWS_MAX];
// GEMM1 B fragments: [ks][hi/lo][ntile][lane][2]
__device__ __align__(16) uint32_t g_Bfrag[(size_t)KSTEPS * KSTEP_U32];
// GEMM2 B fragments (T table): [nt][ks][hi/lo][lane][2]
__device__ __align__(16) uint32_t g_Tfrag[(size_t)TFRAG_U32];

// ---- helpers ----
__device__ __forceinline__ uint32_t smem_u32(const void* p) {
    uint32_t a;
    asm("{ .reg .u64 t; cvta.to.shared.u64 t, %1; cvt.u32.u64 %0, t; }" : "=r"(a) : "l"(p));
    return a;
}
__device__ __forceinline__ uint32_t pack_hi(float2 v) {
    __nv_bfloat162 h = __floats2bfloat162_rn(v.x, v.y);
    return *(uint32_t*)&h;
}
__device__ __forceinline__ uint32_t pack_lo(float2 v, uint32_t hp) {
    __nv_bfloat162 h = *(__nv_bfloat162*)&hp;
    float rx = v.x - __bfloat162float(h.x);
    float ry = v.y - __bfloat162float(h.y);
    __nv_bfloat162 lo = __floats2bfloat162_rn(rx, ry);
    return *(uint32_t*)&lo;
}
__device__ __forceinline__ void mma_bf16(float* c, uint32_t a0, uint32_t a1,
                                         uint32_t a2, uint32_t a3,
                                         uint32_t b0, uint32_t b1) {
    asm volatile(
        "mma.sync.aligned.m16n8k16.row.col.f32.bf16.bf16.f32 "
        "{%0,%1,%2,%3}, {%4,%5,%6,%7}, {%8,%9}, {%0,%1,%2,%3};"
        : "+f"(c[0]), "+f"(c[1]), "+f"(c[2]), "+f"(c[3])
        : "r"(a0), "r"(a1), "r"(a2), "r"(a3), "r"(b0), "r"(b1));
}
#define CPA16(dst_u32, src_ptr) \
    asm volatile("cp.async.cg.shared.global [%0], [%1], 16;" :: "r"(dst_u32), "l"(src_ptr) : "memory")
#define CPA_COMMIT() asm volatile("cp.async.commit_group;" ::: "memory")
#define CPA_WAIT2()  asm volatile("cp.async.wait_group 2;" ::: "memory")
#define CPA_WAIT1()  asm volatile("cp.async.wait_group 1;" ::: "memory")
#define CPA_WAIT0()  asm volatile("cp.async.wait_group 0;" ::: "memory")

// ============================================================
// Kernel 0: column sums of cos/sin table (CS/SS only)
// ============================================================
__global__ void table_kernel() {
    const int f = blockIdx.x;
    const int d = threadIdx.x;
    float center = -1.0f + (2 * d + 1) * (1.0f / 512.0f);
    float arg = center * (float)(f + 1);
    float s, c;
    sincospif(arg, &s, &c);

    __shared__ float sc[512], ss[512];
    sc[d] = c;
    ss[d] = s;
    __syncthreads();
    for (int off = 256; off > 0; off >>= 1) {
        if (d < off) {
            sc[d] += sc[d + off];
            ss[d] += ss[d + off];
        }
        __syncthreads();
    }
    if (d == 0) {
        g_CS[f] = sc[0];
        g_SS[f] = ss[0];
    }
}

// ============================================================
// Kernel 0b: W -> bf16 hi/lo mma B-fragments (GEMM1)
// ============================================================
__global__ void wprep_kernel(const float* __restrict__ Wm) {
    const int ks = blockIdx.x;
    const int nt = threadIdx.x >> 5;
    const int lane = threadIdx.x & 31;
    const int n = nt * 8 + (lane >> 2);
    const int kc = ks * 16 + (lane & 3) * 2;
    float2 wa = make_float2(0.f, 0.f), wb = make_float2(0.f, 0.f);
    if (n < N1) {
        const float* wr = Wm + (size_t)n * DIN;
        wa = make_float2(wr[kc], wr[kc + 1]);
        wb = make_float2(wr[kc + 8], wr[kc + 9]);
    }
    uint32_t h0 = pack_hi(wa), h1 = pack_hi(wb);
    uint32_t l0 = pack_lo(wa, h0), l1 = pack_lo(wb, h1);
    size_t bh = ((((size_t)ks * 2 + 0) * NTILES + nt) * 32 + lane) * 2;
    size_t bl = ((((size_t)ks * 2 + 1) * NTILES + nt) * 32 + lane) * 2;
    g_Bfrag[bh] = h0;
    g_Bfrag[bh + 1] = h1;
    g_Bfrag[bl] = l0;
    g_Bfrag[bl + 1] = l1;
}

// ============================================================
// Kernel 0c: T table -> bf16 hi/lo mma B-fragments (GEMM2)
// ============================================================
__device__ __forceinline__ float tval(int k, float center) {
    float s, c;
    if (k < F) {
        sincospif(center * (float)(k + 1), &s, &c);
        return c;
    } else {
        sincospif(center * (float)(k - F + 1), &s, &c);
        return -s;
    }
}
__global__ void tprep_kernel() {
    const int nt = blockIdx.x;
    const int ks = threadIdx.x >> 5;
    const int lane = threadIdx.x & 31;
    const int n = nt * 8 + (lane >> 2);
    const int kc = ks * 16 + (lane & 3) * 2;
    float center = -1.0f + (2 * n + 1) * (1.0f / 512.0f);
    float2 va = make_float2(tval(kc, center), tval(kc + 1, center));
    float2 vb = make_float2(tval(kc + 8, center), tval(kc + 9, center));
    uint32_t h0 = pack_hi(va), h1 = pack_hi(vb);
    uint32_t l0 = pack_lo(va, h0), l1 = pack_lo(vb, h1);
    size_t base = ((size_t)nt * G2_KS + ks) * 2;
    size_t bh = (base * 32 + lane) * 2;
    size_t bl = ((base + 1) * 32 + lane) * 2;
    g_Tfrag[bh] = h0;
    g_Tfrag[bh + 1] = h1;
    g_Tfrag[bl] = l0;
    g_Tfrag[bl + 1] = l1;
}

// ============================================================
// Kernel 1 (HMMA, cp.async pipelined, 3 CTAs/SM):
// M=32 rows/CTA (2048 blocks -> 92% wave utilization at 444 concurrent).
// 8 warps = 2 row-slices (16 rows) x 4 ntile-groups ({5,4,4,4} over 17).
// One row-slice per warp (R11 layout). Epilogue: interleaved-complex autocorr.
// ============================================================
constexpr int SM_PZ    = 0;                          // 32 x 66 float2 = 16896
constexpr int SM_CONTR = 16896;                      // 32*64 f32 -> 25088
constexpr int SM_INVR  = 25088;                      // 32 f32 -> 25216
// ring occupies [0, 47104); overlay above fits inside
constexpr int SM_BIAS  = 4 * G1_STAGE;               // 47104, 136 f32 -> 47648
constexpr int SM1_BYTES = 47648 + 64;

__global__ void __launch_bounds__(256, 3)
gemm1_mma_kernel(const float* __restrict__ X, const float* __restrict__ bias) {
    extern __shared__ char sm[];
    const uint32_t sb = smem_u32(sm);
    const int tid = threadIdx.x;
    const int w = tid >> 5;
    const int lane = tid & 31;
    const int ng = w >> 1;           // ntile group 0..3
    const int rs = w & 1;            // row slice (16 rows)
    const int m0 = blockIdx.x * M_CTA;

    if (tid < 136) ((float*)(sm + SM_BIAS))[tid] = (tid < N1) ? bias[tid] : 0.0f;

    const int NT_MY = (ng == 0) ? 5 : 4;
    const int NT0   = (ng == 0) ? 0 : 1 + ng * 4;    // 0,5,9,13

    float acc[5][4];
#pragma unroll
    for (int nt = 0; nt < 5; nt++)
#pragma unroll
        for (int i = 0; i < 4; i++) acc[nt][i] = 0.0f;

    const char* gB = (const char*)g_Bfrag;

    // stage copy: B chunk ids [0,544), X chunk ids [544,672)
    auto copy_stage = [&](int s, int buf) {
        const uint32_t dstb = sb + buf * G1_STAGE;
        const char* srcB = gB + (size_t)s * G1_BST;
#pragma unroll
        for (int it = 0; it < 3; it++) {
            int i = tid + 256 * it;
            if (i < G1_BCH) {
                CPA16(dstb + i * 16, srcB + i * 16);
            } else if (i < G1_CHUNKS) {
                int j = i - G1_BCH;
                int row = j >> 2;
                int c4 = j & 3;
                const float* src = X + (size_t)(m0 + row) * DIN + s * 16 + c4 * 4;
                CPA16(dstb + G1_BST + row * G1_XROWB + c4 * 16, src);
            }
        }
    };

    copy_stage(0, 0); CPA_COMMIT();
    copy_stage(1, 1); CPA_COMMIT();
    copy_stage(2, 2); CPA_COMMIT();

    const int xoff = (rs * 16 + (lane >> 2)) * G1_XROWB + (lane & 3) * 8;

    for (int s = 0; s < KSTEPS; s++) {
        if (s < KSTEPS - 2)       { CPA_WAIT2(); }
        else if (s == KSTEPS - 2) { CPA_WAIT1(); }
        else                      { CPA_WAIT0(); }
        __syncthreads();
        if (s + 3 < KSTEPS) {
            copy_stage(s + 3, (s + 3) & 3);
            CPA_COMMIT();
        }

        const char* bb = sm + (s & 3) * G1_STAGE;
        const char* xb = bb + G1_BST + xoff;
        float2 v1a = *(const float2*)(xb);
        float2 v1b = *(const float2*)(xb + 32);
        float2 v2a = *(const float2*)(xb + 8 * G1_XROWB);
        float2 v2b = *(const float2*)(xb + 8 * G1_XROWB + 32);
        uint32_t ah0 = pack_hi(v1a), ah1 = pack_hi(v2a);
        uint32_t ah2 = pack_hi(v1b), ah3 = pack_hi(v2b);
        uint32_t al0 = pack_lo(v1a, ah0), al1 = pack_lo(v2a, ah1);
        uint32_t al2 = pack_lo(v1b, ah2), al3 = pack_lo(v2b, ah3);

        const char* kbase = bb + lane * 8 + NT0 * 256;
#pragma unroll
        for (int nt = 0; nt < 5; nt++) {
            if (nt < NT_MY) {
                uint2 bh = *(const uint2*)(kbase + nt * 256);
                uint2 bl = *(const uint2*)(kbase + NTILES * 256 + nt * 256);
                mma_bf16(acc[nt], ah0, ah1, ah2, ah3, bh.x, bh.y);
                mma_bf16(acc[nt], ah0, ah1, ah2, ah3, bl.x, bl.y);
                mma_bf16(acc[nt], al0, al1, al2, al3, bh.x, bh.y);
            }
        }
    }
    __syncthreads();   // ring dead; overlay pz

    // ---- scatter acc (+bias) into interleaved pz[row][c] ----
    // c < 65: z.x = p[c];  c >= 65: z[c-65].y = p[c]
    float* pzf = (float*)(sm + SM_PZ);
    float* sbias = (float*)(sm + SM_BIAS);
    {
        const int r1 = rs * 16 + (lane >> 2);
        const int cb = (lane & 3) * 2;
#pragma unroll
        for (int nt = 0; nt < 5; nt++) {
            if (nt < NT_MY) {
                int col0 = (NT0 + nt) * 8 + cb;
#pragma unroll
                for (int h = 0; h < 2; h++) {
                    int col = col0 + h;
                    if (col < N1) {
                        float bv = sbias[col];
                        float v0 = acc[nt][h] + bv;       // row r1
                        float v1 = acc[nt][2 + h] + bv;   // row r1+8
                        int ci = (col < L) ? col * 2 : (col - L) * 2 + 1;
                        pzf[r1 * 132 + ci] = v0;
                        pzf[(r1 + 8) * 132 + ci] = v1;
                    }
                }
            }
        }
    }
    __syncthreads();

    // ---- autocorrelation (block-local, interleaved complex) ----
    const float2* pz = (const float2*)(sm + SM_PZ);
    float* contrib = (float*)(sm + SM_CONTR);
    float* inv_r0 = (float*)(sm + SM_INVR);

    if (tid < M_CTA) {
        const float2* zr = pz + tid * 66;
        float s = 0.0f;
        for (int j = 0; j < L; j++) {
            float2 u = zr[j];
            s += u.x * u.x + u.y * u.y;
        }
        inv_r0[tid] = 1.0f / s;
    }
    __syncthreads();

    for (int t = tid; t < M_CTA * 64; t += 256) {
        int row = t >> 6;
        int lag = 1 + (t & 63);
        const float2* zr = pz + row * 66;
        float sre = 0.0f, sim = 0.0f;
        int n = L - lag;
        for (int j = 0; j < n; j++) {
            float2 u = zr[j + lag];
            float2 v = zr[j];
            sre += u.x * v.x + u.y * v.y;
            sim += u.y * v.x - u.x * v.y;
        }
        float ir = inv_r0[row];
        float cr = sre * ir;
        float ci = sim * ir;
        size_t base = (size_t)(m0 + row) * K2;
        __nv_bfloat16 crh = __float2bfloat16(cr);
        __nv_bfloat16 cih = __float2bfloat16(ci);
        g_coefh[base + (lag - 1)]     = crh;
        g_coefh[base + F + (lag - 1)] = cih;
        g_coefl[base + (lag - 1)]     = __float2bfloat16(cr - __bfloat162float(crh));
        g_coefl[base + F + (lag - 1)] = __float2bfloat16(ci - __bfloat162float(cih));
        contrib[row * 64 + (lag - 1)] = cr * g_CS[lag - 1] - ci * g_SS[lag - 1];
    }
    __syncthreads();

    if (tid < M_CTA) {
        const float* cb = contrib + tid * 64;
        float S = 0.5f * (float)D;
        for (int k = 0; k < 64; k++) S += cb[k];
        g_invS[m0 + tid] = 1.0f / S;
    }
}

// ============================================================
// Kernel 2 (HMMA): like = coef @ T (+0.5) -> log epilogue
// ============================================================
__global__ void __launch_bounds__(256)
gemm2_mma_kernel(float* __restrict__ out) {
    extern __shared__ char sm[];
    uint32_t* smB = (uint32_t*)sm;
    const int tid = threadIdx.x;
    const int w = tid >> 5;
    const int lane = tid & 31;
    const int m0 = blockIdx.x * 128;
    const int nb = blockIdx.y;

    {
        const uint4* src = (const uint4*)(g_Tfrag + (size_t)nb * SM2_U32);
        uint4* dst = (uint4*)smB;
        for (int i = tid; i < SM2_U32 / 4; i += 256) dst[i] = src[i];
    }
    __syncthreads();

    float acc[G2_NT][4];
#pragma unroll
    for (int nt = 0; nt < G2_NT; nt++)
#pragma unroll
        for (int i = 0; i < 4; i++) acc[nt][i] = 0.0f;

    const int r1 = m0 + w * 16 + (lane >> 2);
    const __nv_bfloat16* ch1 = g_coefh + (size_t)r1 * K2;
    const __nv_bfloat16* ch2 = ch1 + 8 * K2;
    const __nv_bfloat16* cl1 = g_coefl + (size_t)r1 * K2;
    const __nv_bfloat16* cl2 = cl1 + 8 * K2;
    const int kc0 = (lane & 3) * 2;

#pragma unroll
    for (int ks = 0; ks < G2_KS; ks++) {
        const int kc = ks * 16 + kc0;
        uint32_t ah0 = *(const uint32_t*)(ch1 + kc);
        uint32_t ah1 = *(const uint32_t*)(ch2 + kc);
        uint32_t ah2 = *(const uint32_t*)(ch1 + kc + 8);
        uint32_t ah3 = *(const uint32_t*)(ch2 + kc + 8);
        uint32_t al0 = *(const uint32_t*)(cl1 + kc);
        uint32_t al1 = *(const uint32_t*)(cl2 + kc);
        uint32_t al2 = *(const uint32_t*)(cl1 + kc + 8);
        uint32_t al3 = *(const uint32_t*)(cl2 + kc + 8);
#pragma unroll
        for (int nt = 0; nt < G2_NT; nt++) {
            const uint32_t* p = smB + (((nt * G2_KS + ks) * 2) * 32 + lane) * 2;
            uint2 bh = *(const uint2*)p;
            uint2 bl = *(const uint2*)(p + 64);
            mma_bf16(acc[nt], ah0, ah1, ah2, ah3, bh.x, bh.y);
            mma_bf16(acc[nt], ah0, ah1, ah2, ah3, bl.x, bl.y);
            mma_bf16(acc[nt], al0, al1, al2, al3, bh.x, bh.y);
        }
    }

    const float is0 = g_invS[r1];
    const float is1 = g_invS[r1 + 8];
    float* o0 = out + (size_t)r1 * D + nb * 128 + kc0;
    float* o1 = o0 + 8 * (size_t)D;
#pragma unroll
    for (int nt = 0; nt < G2_NT; nt++) {
        float2 u0, u1;
        u0.x = __logf(fmaf(acc[nt][0] + 0.5f, is0, 1e-5f));
        u0.y = __logf(fmaf(acc[nt][1] + 0.5f, is0, 1e-5f));
        u1.x = __logf(fmaf(acc[nt][2] + 0.5f, is1, 1e-5f));
        u1.y = __logf(fmaf(acc[nt][3] + 0.5f, is1, 1e-5f));
        *(float2*)(o0 + nt * 8) = u0;
        *(float2*)(o1 + nt * 8) = u1;
    }
}

extern "C" void kernel_launch(void* const* d_in, const int* in_sizes, int n_in,
                              void* d_out, int out_size) {
    const float* X = (const float*)d_in[0];     // batch [16,4096,1024]
    const float* Wm = (const float*)d_in[1];    // W [130,1024]
    const float* bias = (const float*)d_in[2];  // b [130]
    float* out = (float*)d_out;                 // [16,4096,512] f32

    const int rows = in_sizes[0] / DIN;         // 65536

    static bool attr_set = false;
    if (!attr_set) {
        cudaFuncSetAttribute(gemm1_mma_kernel,
                             cudaFuncAttributeMaxDynamicSharedMemorySize, SM1_BYTES);
        cudaFuncSetAttribute(gemm2_mma_kernel,
                             cudaFuncAttributeMaxDynamicSharedMemorySize, SM2_BYTES);
        attr_set = true;
    }

    table_kernel<<<F, D>>>();
    wprep_kernel<<<KSTEPS, NTILES * 32>>>(Wm);
    tprep_kernel<<<64, 256>>>();
    gemm1_mma_kernel<<<rows / M_CTA, 256, SM1_BYTES>>>(X, bias);
    gemm2_mma_kernel<<<dim3(rows / 128, 4), 256, SM2_BYTES>>>(out);
}

// round 14
// speedup vs baseline: 1.6895x; 1.6895x over previous
#include <cuda_runtime.h>
#include <cuda_bf16.h>
#include <cstdint>

// Problem constants (fixed shapes)
constexpr int DIN      = 1024;   // input dim
constexpr int L        = 65;     // NUM_FREQ + 1
constexpr int N1       = 130;    // 2L (GEMM1 output cols)
constexpr int F        = 64;     // NUM_FREQ
constexpr int K2       = 128;    // 2F (GEMM2 reduction)
constexpr int D        = 512;    // DIM_OUTPUT
constexpr int ROWS_MAX = 65536;  // 16 * 4096

// GEMM1 mma tiling: M=64 per CTA; warps 0-3: ntiles 0-8, warps 4-7: ntiles 9-16
constexpr int NTILES  = 17;            // 136 cols / 8
constexpr int KSTEPS  = 64;            // 1024 / 16, one kstep per pipeline stage
constexpr int KSTEP_U32 = 2 * NTILES * 32 * 2;       // 2176 u32 = 8704 B per kstep (B frags)
constexpr int M_CTA   = 64;

// gemm1 pipeline: 3-buffer ring, 1 kstep per stage
constexpr int G1_BST   = 8704;             // B bytes per stage
constexpr int G1_XROWB = 96;               // X smem row stride (2-way conflicts max)
constexpr int G1_XST   = M_CTA * G1_XROWB; // 6144 B per stage
constexpr int G1_STAGE = G1_BST + G1_XST;  // 14848
constexpr int G1_BCH   = G1_BST / 16;      // 544 16B chunks
constexpr int G1_XDATA = M_CTA * 4;        // 256 chunks (4 x 16B per row)
constexpr int G1_CHUNKS = G1_BCH + G1_XDATA;   // 800

// GEMM2 mma tiling: per CTA 128 rows x 128 cols, K=128 (8 ksteps), 16 ntiles
constexpr int G2_NT   = 16;
constexpr int G2_KS   = 8;
constexpr int TFRAG_U32_PER_NT = G2_KS * 2 * 32 * 2;     // 1024 u32 per (global) ntile
constexpr int TFRAG_U32 = 64 * TFRAG_U32_PER_NT;         // 65536 u32 = 256 KB total
constexpr int SM2_U32  = G2_NT * TFRAG_U32_PER_NT;       // 16384 u32 = 64 KB per CTA
constexpr int SM2_BYTES = SM2_U32 * 4;

// Scratch (static device globals — no runtime allocation)
__device__ __align__(16) __nv_bfloat16 g_coefh[(size_t)ROWS_MAX * K2];
__device__ __align__(16) __nv_bfloat16 g_coefl[(size_t)ROWS_MAX * K2];
__device__ float g_CS[F];
__device__ float g_SS[F];
__device__ float g_invS[ROWS_MAX];
// GEMM1 B fragments: [ks][hi/lo][ntile][lane][2]
__device__ __align__(16) uint32_t g_Bfrag[(size_t)KSTEPS * KSTEP_U32];
// GEMM2 B fragments (T table): [nt][ks][hi/lo][lane][2]
__device__ __align__(16) uint32_t g_Tfrag[(size_t)TFRAG_U32];

// ---- helpers ----
__device__ __forceinline__ uint32_t smem_u32(const void* p) {
    uint32_t a;
    asm("{ .reg .u64 t; cvta.to.shared.u64 t, %1; cvt.u32.u64 %0, t; }" : "=r"(a) : "l"(p));
    return a;
}
__device__ __forceinline__ uint32_t pack_hi(float2 v) {
    __nv_bfloat162 h = __floats2bfloat162_rn(v.x, v.y);
    return *(uint32_t*)&h;
}
__device__ __forceinline__ uint32_t pack_lo(float2 v, uint32_t hp) {
    __nv_bfloat162 h = *(__nv_bfloat162*)&hp;
    float rx = v.x - __bfloat162float(h.x);
    float ry = v.y - __bfloat162float(h.y);
    __nv_bfloat162 lo = __floats2bfloat162_rn(rx, ry);
    return *(uint32_t*)&lo;
}
__device__ __forceinline__ void mma_bf16(float* c, uint32_t a0, uint32_t a1,
                                         uint32_t a2, uint32_t a3,
                                         uint32_t b0, uint32_t b1) {
    asm volatile(
        "mma.sync.aligned.m16n8k16.row.col.f32.bf16.bf16.f32 "
        "{%0,%1,%2,%3}, {%4,%5,%6,%7}, {%8,%9}, {%0,%1,%2,%3};"
        : "+f"(c[0]), "+f"(c[1]), "+f"(c[2]), "+f"(c[3])
        : "r"(a0), "r"(a1), "r"(a2), "r"(a3), "r"(b0), "r"(b1));
}
#define CPA16(dst_u32, src_ptr) \
    asm volatile("cp.async.cg.shared.global [%0], [%1], 16;" :: "r"(dst_u32), "l"(src_ptr) : "memory")
#define CPA_COMMIT() asm volatile("cp.async.commit_group;" ::: "memory")
#define CPA_WAIT1()  asm volatile("cp.async.wait_group 1;" ::: "memory")
#define CPA_WAIT0()  asm volatile("cp.async.wait_group 0;" ::: "memory")

// ============================================================
// Kernel 0: column sums of cos/sin table (CS/SS only)
// ============================================================
__global__ void table_kernel() {
    const int f = blockIdx.x;
    const int d = threadIdx.x;
    float center = -1.0f + (2 * d + 1) * (1.0f / 512.0f);
    float arg = center * (float)(f + 1);
    float s, c;
    sincospif(arg, &s, &c);

    __shared__ float sc[512], ss[512];
    sc[d] = c;
    ss[d] = s;
    __syncthreads();
    for (int off = 256; off > 0; off >>= 1) {
        if (d < off) {
            sc[d] += sc[d + off];
            ss[d] += ss[d + off];
        }
        __syncthreads();
    }
    if (d == 0) {
        g_CS[f] = sc[0];
        g_SS[f] = ss[0];
    }
}

// ============================================================
// Kernel 0b: W -> bf16 hi/lo mma B-fragments (GEMM1)
// ============================================================
__global__ void wprep_kernel(const float* __restrict__ Wm) {
    const int ks = blockIdx.x;
    const int nt = threadIdx.x >> 5;
    const int lane = threadIdx.x & 31;
    const int n = nt * 8 + (lane >> 2);
    const int kc = ks * 16 + (lane & 3) * 2;
    float2 wa = make_float2(0.f, 0.f), wb = make_float2(0.f, 0.f);
    if (n < N1) {
        const float* wr = Wm + (size_t)n * DIN;
        wa = make_float2(wr[kc], wr[kc + 1]);
        wb = make_float2(wr[kc + 8], wr[kc + 9]);
    }
    uint32_t h0 = pack_hi(wa), h1 = pack_hi(wb);
    uint32_t l0 = pack_lo(wa, h0), l1 = pack_lo(wb, h1);
    size_t bh = ((((size_t)ks * 2 + 0) * NTILES + nt) * 32 + lane) * 2;
    size_t bl = ((((size_t)ks * 2 + 1) * NTILES + nt) * 32 + lane) * 2;
    g_Bfrag[bh] = h0;
    g_Bfrag[bh + 1] = h1;
    g_Bfrag[bl] = l0;
    g_Bfrag[bl + 1] = l1;
}

// ============================================================
// Kernel 0c: T table -> bf16 hi/lo mma B-fragments (GEMM2)
// ============================================================
__device__ __forceinline__ float tval(int k, float center) {
    float s, c;
    if (k < F) {
        sincospif(center * (float)(k + 1), &s, &c);
        return c;
    } else {
        sincospif(center * (float)(k - F + 1), &s, &c);
        return -s;
    }
}
__global__ void tprep_kernel() {
    const int nt = blockIdx.x;
    const int ks = threadIdx.x >> 5;
    const int lane = threadIdx.x & 31;
    const int n = nt * 8 + (lane >> 2);
    const int kc = ks * 16 + (lane & 3) * 2;
    float center = -1.0f + (2 * n + 1) * (1.0f / 512.0f);
    float2 va = make_float2(tval(kc, center), tval(kc + 1, center));
    float2 vb = make_float2(tval(kc + 8, center), tval(kc + 9, center));
    uint32_t h0 = pack_hi(va), h1 = pack_hi(vb);
    uint32_t l0 = pack_lo(va, h0), l1 = pack_lo(vb, h1);
    size_t base = ((size_t)nt * G2_KS + ks) * 2;
    size_t bh = (base * 32 + lane) * 2;
    size_t bl = ((base + 1) * 32 + lane) * 2;
    g_Tfrag[bh] = h0;
    g_Tfrag[bh + 1] = h1;
    g_Tfrag[bl] = l0;
    g_Tfrag[bl + 1] = l1;
}

// ============================================================
// Kernel 1 (HMMA, cp.async 3-stage ring, 4 CTAs/SM):
// M=64 rows/CTA; warps 0-3: ntiles 0-8, warps 4-7: ntiles 9-16,
// (w&3) selects 16-row slice. Specialized (branch-free) ntile loops.
// Epilogue: interleaved-complex autocorr.
// ============================================================
constexpr int SM_PZ    = 0;                          // 64 x 66 float2 = 33792
constexpr int SM_CONTR = 33792;                      // 64*64 f32 -> 50176
constexpr int SM_INVR  = 50176;                      // 64 f32 -> 50432
constexpr int SM_BIAS  = 50432;                      // 136 f32 -> 50976 (beyond ring+overlay)
constexpr int SM1_BYTES = 50976 + 64;
// ring occupies [0, 44544); overlay [0, 50432) used only after mainloop

__global__ void __launch_bounds__(256, 4)
gemm1_mma_kernel(const float* __restrict__ X, const float* __restrict__ bias) {
    extern __shared__ char sm[];
    const uint32_t sb = smem_u32(sm);
    const int tid = threadIdx.x;
    const int w = tid >> 5;
    const int lane = tid & 31;
    const int wg = w >> 2;           // 0: nt 0-8, 1: nt 9-16
    const int wr = w & 3;            // 16-row slice
    const int m0 = blockIdx.x * M_CTA;

    if (tid < 136) ((float*)(sm + SM_BIAS))[tid] = (tid < N1) ? bias[tid] : 0.0f;

    float acc[9][4];
#pragma unroll
    for (int nt = 0; nt < 9; nt++)
#pragma unroll
        for (int i = 0; i < 4; i++) acc[nt][i] = 0.0f;

    const char* gB = (const char*)g_Bfrag;

    // stage copy: B chunk ids [0,544), X chunk ids [544,800)
    auto copy_stage = [&](int s, int buf) {
        const uint32_t dstb = sb + buf * G1_STAGE;
        const char* srcB = gB + (size_t)s * G1_BST;
#pragma unroll
        for (int it = 0; it < 4; it++) {
            int i = tid + 256 * it;
            if (i < G1_BCH) {
                CPA16(dstb + i * 16, srcB + i * 16);
            } else if (i < G1_CHUNKS) {
                int j = i - G1_BCH;
                int row = j >> 2;
                int c4 = j & 3;
                const float* src = X + (size_t)(m0 + row) * DIN + s * 16 + c4 * 4;
                CPA16(dstb + G1_BST + row * G1_XROWB + c4 * 16, src);
            }
        }
    };

    copy_stage(0, 0); CPA_COMMIT();
    copy_stage(1, 1); CPA_COMMIT();

    const int xoff = (wr * 16 + (lane >> 2)) * G1_XROWB + (lane & 3) * 8;

    int cur = 0;                     // buffer of stage s
    for (int s = 0; s < KSTEPS; s++) {
        if (s < KSTEPS - 1) { CPA_WAIT1(); }
        else                { CPA_WAIT0(); }
        __syncthreads();
        if (s + 2 < KSTEPS) {
            int tgt = cur ? cur - 1 : 2;     // (cur + 2) % 3
            copy_stage(s + 2, tgt);
            CPA_COMMIT();
        }

        const char* bb = sm + cur * G1_STAGE;
        const char* xb = bb + G1_BST + xoff;
        float2 v1a = *(const float2*)(xb);
        float2 v1b = *(const float2*)(xb + 32);
        float2 v2a = *(const float2*)(xb + 8 * G1_XROWB);
        float2 v2b = *(const float2*)(xb + 8 * G1_XROWB + 32);
        uint32_t ah0 = pack_hi(v1a), ah1 = pack_hi(v2a);
        uint32_t ah2 = pack_hi(v1b), ah3 = pack_hi(v2b);
        uint32_t al0 = pack_lo(v1a, ah0), al1 = pack_lo(v2a, ah1);
        uint32_t al2 = pack_lo(v1b, ah2), al3 = pack_lo(v2b, ah3);

        const char* kbase = bb + lane * 8;
        if (wg == 0) {
#pragma unroll
            for (int nt = 0; nt < 9; nt++) {
                uint2 bh = *(const uint2*)(kbase + nt * 256);
                uint2 bl = *(const uint2*)(kbase + NTILES * 256 + nt * 256);
                mma_bf16(acc[nt], ah0, ah1, ah2, ah3, bh.x, bh.y);
                mma_bf16(acc[nt], ah0, ah1, ah2, ah3, bl.x, bl.y);
                mma_bf16(acc[nt], al0, al1, al2, al3, bh.x, bh.y);
            }
        } else {
#pragma unroll
            for (int nt = 0; nt < 8; nt++) {
                uint2 bh = *(const uint2*)(kbase + (9 + nt) * 256);
                uint2 bl = *(const uint2*)(kbase + NTILES * 256 + (9 + nt) * 256);
                mma_bf16(acc[nt], ah0, ah1, ah2, ah3, bh.x, bh.y);
                mma_bf16(acc[nt], ah0, ah1, ah2, ah3, bl.x, bl.y);
                mma_bf16(acc[nt], al0, al1, al2, al3, bh.x, bh.y);
            }
        }
        cur = (cur == 2) ? 0 : cur + 1;
    }
    __syncthreads();   // ring dead; overlay pz

    // ---- scatter acc (+bias) into interleaved pz[row][c] ----
    // c < 65: z.x = p[c];  c >= 65: z[c-65].y = p[c]
    float* pzf = (float*)(sm + SM_PZ);
    float* sbias = (float*)(sm + SM_BIAS);
    {
        const int r1 = wr * 16 + (lane >> 2);
        const int cb = (lane & 3) * 2;
        const int NT_MY = wg ? 8 : 9;
        const int NT0 = wg ? 9 : 0;
#pragma unroll
        for (int nt = 0; nt < 9; nt++) {
            if (nt < NT_MY) {
                int col0 = (NT0 + nt) * 8 + cb;
#pragma unroll
                for (int h = 0; h < 2; h++) {
                    int col = col0 + h;
                    if (col < N1) {
                        float bv = sbias[col];
                        float v0 = acc[nt][h] + bv;       // row r1
                        float v1 = acc[nt][2 + h] + bv;   // row r1+8
                        int ci = (col < L) ? col * 2 : (col - L) * 2 + 1;
                        pzf[r1 * 132 + ci] = v0;
                        pzf[(r1 + 8) * 132 + ci] = v1;
                    }
                }
            }
        }
    }
    __syncthreads();

    // ---- autocorrelation (block-local, interleaved complex) ----
    const float2* pz = (const float2*)(sm + SM_PZ);
    float* contrib = (float*)(sm + SM_CONTR);
    float* inv_r0 = (float*)(sm + SM_INVR);

    if (tid < M_CTA) {
        const float2* zr = pz + tid * 66;
        float s = 0.0f;
        for (int j = 0; j < L; j++) {
            float2 u = zr[j];
            s += u.x * u.x + u.y * u.y;
        }
        inv_r0[tid] = 1.0f / s;
    }
    __syncthreads();

    for (int t = tid; t < M_CTA * 64; t += 256) {
        int row = t >> 6;
        int lag = 1 + (t & 63);
        const float2* zr = pz + row * 66;
        float sre = 0.0f, sim = 0.0f;
        int n = L - lag;
        for (int j = 0; j < n; j++) {
            float2 u = zr[j + lag];
            float2 v = zr[j];
            sre += u.x * v.x + u.y * v.y;
            sim += u.y * v.x - u.x * v.y;
        }
        float ir = inv_r0[row];
        float cr = sre * ir;
        float ci = sim * ir;
        size_t base = (size_t)(m0 + row) * K2;
        __nv_bfloat16 crh = __float2bfloat16(cr);
        __nv_bfloat16 cih = __float2bfloat16(ci);
        g_coefh[base + (lag - 1)]     = crh;
        g_coefh[base + F + (lag - 1)] = cih;
        g_coefl[base + (lag - 1)]     = __float2bfloat16(cr - __bfloat162float(crh));
        g_coefl[base + F + (lag - 1)] = __float2bfloat16(ci - __bfloat162float(cih));
        contrib[row * 64 + (lag - 1)] = cr * g_CS[lag - 1] - ci * g_SS[lag - 1];
    }
    __syncthreads();

    if (tid < M_CTA) {
        const float* cb = contrib + tid * 64;
        float S = 0.5f * (float)D;
        for (int k = 0; k < 64; k++) S += cb[k];
        g_invS[m0 + tid] = 1.0f / S;
    }
}

// ============================================================
// Kernel 2 (HMMA): like = coef @ T (+0.5) -> log epilogue
// ============================================================
__global__ void __launch_bounds__(256)
gemm2_mma_kernel(float* __restrict__ out) {
    extern __shared__ char sm[];
    uint32_t* smB = (uint32_t*)sm;
    const int tid = threadIdx.x;
    const int w = tid >> 5;
    const int lane = tid & 31;
    const int m0 = blockIdx.x * 128;
    const int nb = blockIdx.y;

    {
        const uint4* src = (const uint4*)(g_Tfrag + (size_t)nb * SM2_U32);
        uint4* dst = (uint4*)smB;
        for (int i = tid; i < SM2_U32 / 4; i += 256) dst[i] = src[i];
    }
    __syncthreads();

    float acc[G2_NT][4];
#pragma unroll
    for (int nt = 0; nt < G2_NT; nt++)
#pragma unroll
        for (int i = 0; i < 4; i++) acc[nt][i] = 0.0f;

    const int r1 = m0 + w * 16 + (lane >> 2);
    const __nv_bfloat16* ch1 = g_coefh + (size_t)r1 * K2;
    const __nv_bfloat16* ch2 = ch1 + 8 * K2;
    const __nv_bfloat16* cl1 = g_coefl + (size_t)r1 * K2;
    const __nv_bfloat16* cl2 = cl1 + 8 * K2;
    const int kc0 = (lane & 3) * 2;

#pragma unroll
    for (int ks = 0; ks < G2_KS; ks++) {
        const int kc = ks * 16 + kc0;
        uint32_t ah0 = *(const uint32_t*)(ch1 + kc);
        uint32_t ah1 = *(const uint32_t*)(ch2 + kc);
        uint32_t ah2 = *(const uint32_t*)(ch1 + kc + 8);
        uint32_t ah3 = *(const uint32_t*)(ch2 + kc + 8);
        uint32_t al0 = *(const uint32_t*)(cl1 + kc);
        uint32_t al1 = *(const uint32_t*)(cl2 + kc);
        uint32_t al2 = *(const uint32_t*)(cl1 + kc + 8);
        uint32_t al3 = *(const uint32_t*)(cl2 + kc + 8);
#pragma unroll
        for (int nt = 0; nt < G2_NT; nt++) {
            const uint32_t* p = smB + (((nt * G2_KS + ks) * 2) * 32 + lane) * 2;
            uint2 bh = *(const uint2*)p;
            uint2 bl = *(const uint2*)(p + 64);
            mma_bf16(acc[nt], ah0, ah1, ah2, ah3, bh.x, bh.y);
            mma_bf16(acc[nt], ah0, ah1, ah2, ah3, bl.x, bl.y);
            mma_bf16(acc[nt], al0, al1, al2, al3, bh.x, bh.y);
        }
    }

    const float is0 = g_invS[r1];
    const float is1 = g_invS[r1 + 8];
    float* o0 = out + (size_t)r1 * D + nb * 128 + kc0;
    float* o1 = o0 + 8 * (size_t)D;
#pragma unroll
    for (int nt = 0; nt < G2_NT; nt++) {
        float2 u0, u1;
        u0.x = __logf(fmaf(acc[nt][0] + 0.5f, is0, 1e-5f));
        u0.y = __logf(fmaf(acc[nt][1] + 0.5f, is0, 1e-5f));
        u1.x = __logf(fmaf(acc[nt][2] + 0.5f, is1, 1e-5f));
        u1.y = __logf(fmaf(acc[nt][3] + 0.5f, is1, 1e-5f));
        *(float2*)(o0 + nt * 8) = u0;
        *(float2*)(o1 + nt * 8) = u1;
    }
}

extern "C" void kernel_launch(void* const* d_in, const int* in_sizes, int n_in,
                              void* d_out, int out_size) {
    const float* X = (const float*)d_in[0];     // batch [16,4096,1024]
    const float* Wm = (const float*)d_in[1];    // W [130,1024]
    const float* bias = (const float*)d_in[2];  // b [130]
    float* out = (float*)d_out;                 // [16,4096,512] f32

    const int rows = in_sizes[0] / DIN;         // 65536

    static bool attr_set = false;
    if (!attr_set) {
        cudaFuncSetAttribute(gemm1_mma_kernel,
                             cudaFuncAttributeMaxDynamicSharedMemorySize, SM1_BYTES);
        cudaFuncSetAttribute(gemm2_mma_kernel,
                             cudaFuncAttributeMaxDynamicSharedMemorySize, SM2_BYTES);
        attr_set = true;
    }

    table_kernel<<<F, D>>>();
    wprep_kernel<<<KSTEPS, NTILES * 32>>>(Wm);
    tprep_kernel<<<64, 256>>>();
    gemm1_mma_kernel<<<rows / M_CTA, 256, SM1_BYTES>>>(X, bias);
    gemm2_mma_kernel<<<dim3(rows / 128, 4), 256, SM2_BYTES>>>(out);
}

// round 15
// speedup vs baseline: 1.7449x; 1.0328x over previous
#include <cuda_runtime.h>
#include <cuda_bf16.h>
#include <cstdint>

// Problem constants (fixed shapes)
constexpr int DIN      = 1024;   // input dim
constexpr int L        = 65;     // NUM_FREQ + 1
constexpr int N1       = 130;    // 2L (GEMM1 output cols)
constexpr int F        = 64;     // NUM_FREQ
constexpr int K2       = 128;    // 2F (GEMM2 reduction)
constexpr int D        = 512;    // DIM_OUTPUT
constexpr int ROWS_MAX = 65536;  // 16 * 4096

// GEMM1 mma tiling: M=64 per CTA; warps 0-3: ntiles 0-8, warps 4-7: ntiles 9-16
constexpr int NTILES  = 17;            // 136 cols / 8
constexpr int KSTEPS  = 64;            // 1024 / 16, one kstep per pipeline stage
constexpr int KSTEP_U32 = NTILES * 32 * 4;           // 2176 u32 = 8704 B per kstep (B frags)
constexpr int M_CTA   = 64;

// gemm1 pipeline: 3-buffer ring, 1 kstep per stage
constexpr int G1_BST   = 8704;             // B bytes per stage
constexpr int G1_XROWB = 96;               // X smem row stride (2-way conflicts max)
constexpr int G1_XST   = M_CTA * G1_XROWB; // 6144 B per stage
constexpr int G1_STAGE = G1_BST + G1_XST;  // 14848
constexpr int G1_BCH   = G1_BST / 16;      // 544 16B chunks
constexpr int G1_XDATA = M_CTA * 4;        // 256 chunks (4 x 16B per row)
constexpr int G1_CHUNKS = G1_BCH + G1_XDATA;   // 800

// GEMM2 mma tiling: per CTA 128 rows x 128 cols, K=128 (8 ksteps), 16 ntiles
constexpr int G2_NT   = 16;
constexpr int G2_KS   = 8;
constexpr int TFRAG_U32_PER_NT = G2_KS * 32 * 4;         // 1024 u32 per (global) ntile
constexpr int TFRAG_U32 = 64 * TFRAG_U32_PER_NT;         // 65536 u32 = 256 KB total
constexpr int SM2_U32  = G2_NT * TFRAG_U32_PER_NT;       // 16384 u32 = 64 KB per CTA
constexpr int SM2_BYTES = SM2_U32 * 4;

// Scratch (static device globals — no runtime allocation)
// coef in mma A-fragment layout: [rowblock][ks][lane][reg] u32 (2 bf16 per u32)
constexpr size_t COEF_U32 = (size_t)(ROWS_MAX / 16) * 8 * 32 * 4;
__device__ __align__(16) uint32_t g_coef_fh[COEF_U32];
__device__ __align__(16) uint32_t g_coef_fl[COEF_U32];
__device__ float g_CS[F];
__device__ float g_SS[F];
__device__ float g_invS[ROWS_MAX];
// GEMM1 B fragments: [ks][ntile][lane][4] = {bh0,bh1,bl0,bl1}
__device__ __align__(16) uint32_t g_Bfrag[(size_t)KSTEPS * KSTEP_U32];
// GEMM2 B fragments (T table): [nt][ks][lane][4] = {bh0,bh1,bl0,bl1}
__device__ __align__(16) uint32_t g_Tfrag[(size_t)TFRAG_U32];

// ---- helpers ----
__device__ __forceinline__ uint32_t smem_u32(const void* p) {
    uint32_t a;
    asm("{ .reg .u64 t; cvta.to.shared.u64 t, %1; cvt.u32.u64 %0, t; }" : "=r"(a) : "l"(p));
    return a;
}
__device__ __forceinline__ uint32_t pack_hi(float2 v) {
    __nv_bfloat162 h = __floats2bfloat162_rn(v.x, v.y);
    return *(uint32_t*)&h;
}
__device__ __forceinline__ uint32_t pack_lo(float2 v, uint32_t hp) {
    __nv_bfloat162 h = *(__nv_bfloat162*)&hp;
    float rx = v.x - __bfloat162float(h.x);
    float ry = v.y - __bfloat162float(h.y);
    __nv_bfloat162 lo = __floats2bfloat162_rn(rx, ry);
    return *(uint32_t*)&lo;
}
__device__ __forceinline__ void mma_bf16(float* c, uint32_t a0, uint32_t a1,
                                         uint32_t a2, uint32_t a3,
                                         uint32_t b0, uint32_t b1) {
    asm volatile(
        "mma.sync.aligned.m16n8k16.row.col.f32.bf16.bf16.f32 "
        "{%0,%1,%2,%3}, {%4,%5,%6,%7}, {%8,%9}, {%0,%1,%2,%3};"
        : "+f"(c[0]), "+f"(c[1]), "+f"(c[2]), "+f"(c[3])
        : "r"(a0), "r"(a1), "r"(a2), "r"(a3), "r"(b0), "r"(b1));
}
#define CPA16(dst_u32, src_ptr) \
    asm volatile("cp.async.cg.shared.global [%0], [%1], 16;" :: "r"(dst_u32), "l"(src_ptr) : "memory")
#define CPA_COMMIT() asm volatile("cp.async.commit_group;" ::: "memory")
#define CPA_WAIT1()  asm volatile("cp.async.wait_group 1;" ::: "memory")
#define CPA_WAIT0()  asm volatile("cp.async.wait_group 0;" ::: "memory")

// ============================================================
// Kernel 0: column sums of cos/sin table (CS/SS only)
// ============================================================
__global__ void table_kernel() {
    const int f = blockIdx.x;
    const int d = threadIdx.x;
    float center = -1.0f + (2 * d + 1) * (1.0f / 512.0f);
    float arg = center * (float)(f + 1);
    float s, c;
    sincospif(arg, &s, &c);

    __shared__ float sc[512], ss[512];
    sc[d] = c;
    ss[d] = s;
    __syncthreads();
    for (int off = 256; off > 0; off >>= 1) {
        if (d < off) {
            sc[d] += sc[d + off];
            ss[d] += ss[d + off];
        }
        __syncthreads();
    }
    if (d == 0) {
        g_CS[f] = sc[0];
        g_SS[f] = ss[0];
    }
}

// ============================================================
// Kernel 0b: W -> bf16 hi/lo mma B-fragments (GEMM1)
// layout: [ks][nt][lane][4] = {bh0, bh1, bl0, bl1}
// ============================================================
__global__ void wprep_kernel(const float* __restrict__ Wm) {
    const int ks = blockIdx.x;
    const int nt = threadIdx.x >> 5;
    const int lane = threadIdx.x & 31;
    const int n = nt * 8 + (lane >> 2);
    const int kc = ks * 16 + (lane & 3) * 2;
    float2 wa = make_float2(0.f, 0.f), wb = make_float2(0.f, 0.f);
    if (n < N1) {
        const float* wr = Wm + (size_t)n * DIN;
        wa = make_float2(wr[kc], wr[kc + 1]);
        wb = make_float2(wr[kc + 8], wr[kc + 9]);
    }
    uint32_t h0 = pack_hi(wa), h1 = pack_hi(wb);
    uint32_t l0 = pack_lo(wa, h0), l1 = pack_lo(wb, h1);
    size_t idx = (((size_t)ks * NTILES + nt) * 32 + lane) * 4;
    g_Bfrag[idx + 0] = h0;
    g_Bfrag[idx + 1] = h1;
    g_Bfrag[idx + 2] = l0;
    g_Bfrag[idx + 3] = l1;
}

// ============================================================
// Kernel 0c: T table -> bf16 hi/lo mma B-fragments (GEMM2)
// layout: [nt][ks][lane][4] = {bh0, bh1, bl0, bl1}
// ============================================================
__device__ __forceinline__ float tval(int k, float center) {
    float s, c;
    if (k < F) {
        sincospif(center * (float)(k + 1), &s, &c);
        return c;
    } else {
        sincospif(center * (float)(k - F + 1), &s, &c);
        return -s;
    }
}
__global__ void tprep_kernel() {
    const int nt = blockIdx.x;
    const int ks = threadIdx.x >> 5;
    const int lane = threadIdx.x & 31;
    const int n = nt * 8 + (lane >> 2);
    const int kc = ks * 16 + (lane & 3) * 2;
    float center = -1.0f + (2 * n + 1) * (1.0f / 512.0f);
    float2 va = make_float2(tval(kc, center), tval(kc + 1, center));
    float2 vb = make_float2(tval(kc + 8, center), tval(kc + 9, center));
    uint32_t h0 = pack_hi(va), h1 = pack_hi(vb);
    uint32_t l0 = pack_lo(va, h0), l1 = pack_lo(vb, h1);
    size_t idx = (((size_t)nt * G2_KS + ks) * 32 + lane) * 4;
    g_Tfrag[idx + 0] = h0;
    g_Tfrag[idx + 1] = h1;
    g_Tfrag[idx + 2] = l0;
    g_Tfrag[idx + 3] = l1;
}

// ============================================================
// coef fragment-layout writer: element (grow, col), value v ->
// hi/lo bf16 at [rowblock][ks][lane][reg][half]
// ============================================================
__device__ __forceinline__ void write_coef(int grow, int col, float v) {
    int rb = grow >> 4, r = grow & 15;
    int ks = col >> 4, kc = col & 15;
    int lane2 = (r & 7) * 4 + ((kc & 7) >> 1);
    int reg = (r >> 3) | ((kc >> 3) << 1);
    int half = kc & 1;
    size_t uoff = (((size_t)rb * 8 + ks) * 32 + lane2) * 4 + reg;
    __nv_bfloat16 vh = __float2bfloat16(v);
    ((__nv_bfloat16*)g_coef_fh)[uoff * 2 + half] = vh;
    ((__nv_bfloat16*)g_coef_fl)[uoff * 2 + half] =
        __float2bfloat16(v - __bfloat162float(vh));
}

// ============================================================
// Kernel 1 (HMMA, cp.async 3-stage ring, 4 CTAs/SM):
// M=64 rows/CTA; warps 0-3: ntiles 0-8, warps 4-7: ntiles 9-16,
// (w&3) selects 16-row slice. One LDS.128 per (ntile,kstep) B load.
// Epilogue: interleaved-complex autocorr -> coef fragments + invS.
// ============================================================
constexpr int SM_PZ    = 0;                          // 64 x 66 float2 = 33792
constexpr int SM_CONTR = 33792;                      // 64*64 f32 -> 50176
constexpr int SM_INVR  = 50176;                      // 64 f32 -> 50432
constexpr int SM_BIAS  = 50432;                      // 136 f32 -> 50976
constexpr int SM1_BYTES = 50976 + 64;
// ring occupies [0, 44544); overlay [0, 50432) used only after mainloop

__global__ void __launch_bounds__(256, 4)
gemm1_mma_kernel(const float* __restrict__ X, const float* __restrict__ bias) {
    extern __shared__ char sm[];
    const uint32_t sb = smem_u32(sm);
    const int tid = threadIdx.x;
    const int w = tid >> 5;
    const int lane = tid & 31;
    const int wg = w >> 2;           // 0: nt 0-8, 1: nt 9-16
    const int wr = w & 3;            // 16-row slice
    const int m0 = blockIdx.x * M_CTA;

    if (tid < 136) ((float*)(sm + SM_BIAS))[tid] = (tid < N1) ? bias[tid] : 0.0f;

    float acc[9][4];
#pragma unroll
    for (int nt = 0; nt < 9; nt++)
#pragma unroll
        for (int i = 0; i < 4; i++) acc[nt][i] = 0.0f;

    const char* gB = (const char*)g_Bfrag;

    // stage copy: B chunk ids [0,544), X chunk ids [544,800)
    auto copy_stage = [&](int s, int buf) {
        const uint32_t dstb = sb + buf * G1_STAGE;
        const char* srcB = gB + (size_t)s * G1_BST;
#pragma unroll
        for (int it = 0; it < 4; it++) {
            int i = tid + 256 * it;
            if (i < G1_BCH) {
                CPA16(dstb + i * 16, srcB + i * 16);
            } else if (i < G1_CHUNKS) {
                int j = i - G1_BCH;
                int row = j >> 2;
                int c4 = j & 3;
                const float* src = X + (size_t)(m0 + row) * DIN + s * 16 + c4 * 4;
                CPA16(dstb + G1_BST + row * G1_XROWB + c4 * 16, src);
            }
        }
    };

    copy_stage(0, 0); CPA_COMMIT();
    copy_stage(1, 1); CPA_COMMIT();

    const int xoff = (wr * 16 + (lane >> 2)) * G1_XROWB + (lane & 3) * 8;

    int cur = 0;                     // buffer of stage s
    for (int s = 0; s < KSTEPS; s++) {
        if (s < KSTEPS - 1) { CPA_WAIT1(); }
        else                { CPA_WAIT0(); }
        __syncthreads();
        if (s + 2 < KSTEPS) {
            int tgt = cur ? cur - 1 : 2;     // (cur + 2) % 3
            copy_stage(s + 2, tgt);
            CPA_COMMIT();
        }

        const char* bb = sm + cur * G1_STAGE;
        const char* xb = bb + G1_BST + xoff;
        float2 v1a = *(const float2*)(xb);
        float2 v1b = *(const float2*)(xb + 32);
        float2 v2a = *(const float2*)(xb + 8 * G1_XROWB);
        float2 v2b = *(const float2*)(xb + 8 * G1_XROWB + 32);
        uint32_t ah0 = pack_hi(v1a), ah1 = pack_hi(v2a);
        uint32_t ah2 = pack_hi(v1b), ah3 = pack_hi(v2b);
        uint32_t al0 = pack_lo(v1a, ah0), al1 = pack_lo(v2a, ah1);
        uint32_t al2 = pack_lo(v1b, ah2), al3 = pack_lo(v2b, ah3);

        const char* kbase = bb + lane * 16;
        if (wg == 0) {
#pragma unroll
            for (int nt = 0; nt < 9; nt++) {
                uint4 f = *(const uint4*)(kbase + nt * 512);
                mma_bf16(acc[nt], ah0, ah1, ah2, ah3, f.x, f.y);
                mma_bf16(acc[nt], ah0, ah1, ah2, ah3, f.z, f.w);
                mma_bf16(acc[nt], al0, al1, al2, al3, f.x, f.y);
            }
        } else {
#pragma unroll
            for (int nt = 0; nt < 8; nt++) {
                uint4 f = *(const uint4*)(kbase + (9 + nt) * 512);
                mma_bf16(acc[nt], ah0, ah1, ah2, ah3, f.x, f.y);
                mma_bf16(acc[nt], ah0, ah1, ah2, ah3, f.z, f.w);
                mma_bf16(acc[nt], al0, al1, al2, al3, f.x, f.y);
            }
        }
        cur = (cur == 2) ? 0 : cur + 1;
    }
    __syncthreads();   // ring dead; overlay pz

    // ---- scatter acc (+bias) into interleaved pz[row][c] ----
    // c < 65: z.x = p[c];  c >= 65: z[c-65].y = p[c]
    float* pzf = (float*)(sm + SM_PZ);
    float* sbias = (float*)(sm + SM_BIAS);
    {
        const int r1 = wr * 16 + (lane >> 2);
        const int cb = (lane & 3) * 2;
        const int NT_MY = wg ? 8 : 9;
        const int NT0 = wg ? 9 : 0;
#pragma unroll
        for (int nt = 0; nt < 9; nt++) {
            if (nt < NT_MY) {
                int col0 = (NT0 + nt) * 8 + cb;
#pragma unroll
                for (int h = 0; h < 2; h++) {
                    int col = col0 + h;
                    if (col < N1) {
                        float bv = sbias[col];
                        float v0 = acc[nt][h] + bv;       // row r1
                        float v1 = acc[nt][2 + h] + bv;   // row r1+8
                        int ci = (col < L) ? col * 2 : (col - L) * 2 + 1;
                        pzf[r1 * 132 + ci] = v0;
                        pzf[(r1 + 8) * 132 + ci] = v1;
                    }
                }
            }
        }
    }
    __syncthreads();

    // ---- autocorrelation (block-local, interleaved complex) ----
    const float2* pz = (const float2*)(sm + SM_PZ);
    float* contrib = (float*)(sm + SM_CONTR);
    float* inv_r0 = (float*)(sm + SM_INVR);

    if (tid < M_CTA) {
        const float2* zr = pz + tid * 66;
        float s = 0.0f;
        for (int j = 0; j < L; j++) {
            float2 u = zr[j];
            s += u.x * u.x + u.y * u.y;
        }
        inv_r0[tid] = 1.0f / s;
    }
    __syncthreads();

    for (int t = tid; t < M_CTA * 64; t += 256) {
        int row = t >> 6;
        int lag = 1 + (t & 63);
        const float2* zr = pz + row * 66;
        float sre = 0.0f, sim = 0.0f;
        int n = L - lag;
        for (int j = 0; j < n; j++) {
            float2 u = zr[j + lag];
            float2 v = zr[j];
            sre += u.x * v.x + u.y * v.y;
            sim += u.y * v.x - u.x * v.y;
        }
        float ir = inv_r0[row];
        float cr = sre * ir;
        float ci = sim * ir;
        write_coef(m0 + row, lag - 1, cr);
        write_coef(m0 + row, F + lag - 1, ci);
        contrib[row * 64 + (lag - 1)] = cr * g_CS[lag - 1] - ci * g_SS[lag - 1];
    }
    __syncthreads();

    if (tid < M_CTA) {
        const float* cb = contrib + tid * 64;
        float S = 0.5f * (float)D;
        for (int k = 0; k < 64; k++) S += cb[k];
        g_invS[m0 + tid] = 1.0f / S;
    }
}

// ============================================================
// Kernel 2 (HMMA): like = coef @ T (+0.5) -> log epilogue
// A: 2 LDG.128 per warp per ks (coef fragment layout);
// B: 1 LDS.128 per (ntile, ks).
// ============================================================
__global__ void __launch_bounds__(256)
gemm2_mma_kernel(float* __restrict__ out) {
    extern __shared__ char sm[];
    uint32_t* smB = (uint32_t*)sm;
    const int tid = threadIdx.x;
    const int w = tid >> 5;
    const int lane = tid & 31;
    const int m0 = blockIdx.x * 128;
    const int nb = blockIdx.y;

    {
        const uint4* src = (const uint4*)(g_Tfrag + (size_t)nb * SM2_U32);
        uint4* dst = (uint4*)smB;
        for (int i = tid; i < SM2_U32 / 4; i += 256) dst[i] = src[i];
    }
    __syncthreads();

    float acc[G2_NT][4];
#pragma unroll
    for (int nt = 0; nt < G2_NT; nt++)
#pragma unroll
        for (int i = 0; i < 4; i++) acc[nt][i] = 0.0f;

    const int rb = blockIdx.x * 8 + w;     // global 16-row block
    const uint4* cfh = (const uint4*)g_coef_fh + ((size_t)rb * 8) * 32 + lane;
    const uint4* cfl = (const uint4*)g_coef_fl + ((size_t)rb * 8) * 32 + lane;
    const uint4* smB4 = (const uint4*)smB;

#pragma unroll
    for (int ks = 0; ks < G2_KS; ks++) {
        uint4 Ah = cfh[ks * 32];
        uint4 Al = cfl[ks * 32];
#pragma unroll
        for (int nt = 0; nt < G2_NT; nt++) {
            uint4 f = smB4[(nt * G2_KS + ks) * 32 + lane];
            mma_bf16(acc[nt], Ah.x, Ah.y, Ah.z, Ah.w, f.x, f.y);
            mma_bf16(acc[nt], Ah.x, Ah.y, Ah.z, Ah.w, f.z, f.w);
            mma_bf16(acc[nt], Al.x, Al.y, Al.z, Al.w, f.x, f.y);
        }
    }

    const int r1 = m0 + w * 16 + (lane >> 2);
    const int kc0 = (lane & 3) * 2;
    const float is0 = g_invS[r1];
    const float is1 = g_invS[r1 + 8];
    float* o0 = out + (size_t)r1 * D + nb * 128 + kc0;
    float* o1 = o0 + 8 * (size_t)D;
#pragma unroll
    for (int nt = 0; nt < G2_NT; nt++) {
        float2 u0, u1;
        u0.x = __logf(fmaf(acc[nt][0] + 0.5f, is0, 1e-5f));
        u0.y = __logf(fmaf(acc[nt][1] + 0.5f, is0, 1e-5f));
        u1.x = __logf(fmaf(acc[nt][2] + 0.5f, is1, 1e-5f));
        u1.y = __logf(fmaf(acc[nt][3] + 0.5f, is1, 1e-5f));
        *(float2*)(o0 + nt * 8) = u0;
        *(float2*)(o1 + nt * 8) = u1;
    }
}

extern "C" void kernel_launch(void* const* d_in, const int* in_sizes, int n_in,
                              void* d_out, int out_size) {
    const float* X = (const float*)d_in[0];     // batch [16,4096,1024]
    const float* Wm = (const float*)d_in[1];    // W [130,1024]
    const float* bias = (const float*)d_in[2];  // b [130]
    float* out = (float*)d_out;                 // [16,4096,512] f32

    const int rows = in_sizes[0] / DIN;         // 65536

    static bool attr_set = false;
    if (!attr_set) {
        cudaFuncSetAttribute(gemm1_mma_kernel,
                             cudaFuncAttributeMaxDynamicSharedMemorySize, SM1_BYTES);
        cudaFuncSetAttribute(gemm2_mma_kernel,
                             cudaFuncAttributeMaxDynamicSharedMemorySize, SM2_BYTES);
        attr_set = true;
    }

    table_kernel<<<F, D>>>();
    wprep_kernel<<<KSTEPS, NTILES * 32>>>(Wm);
    tprep_kernel<<<64, 256>>>();
    gemm1_mma_kernel<<<rows / M_CTA, 256, SM1_BYTES>>>(X, bias);
    gemm2_mma_kernel<<<dim3(rows / 128, 4), 256, SM2_BYTES>>>(out);
}

// round 16
// speedup vs baseline: 1.8904x; 1.0834x over previous
#include <cuda_runtime.h>
#include <cuda_bf16.h>
#include <cstdint>

// Problem constants (fixed shapes)
constexpr int DIN      = 1024;   // input dim
constexpr int L        = 65;     // NUM_FREQ + 1
constexpr int N1       = 130;    // 2L (GEMM1 output cols)
constexpr int F        = 64;     // NUM_FREQ
constexpr int K2       = 128;    // 2F (GEMM2 reduction)
constexpr int D        = 512;    // DIM_OUTPUT
constexpr int ROWS_MAX = 65536;  // 16 * 4096

// GEMM1 mma tiling: M=64 per CTA; warps 0-3: ntiles 0-8, warps 4-7: ntiles 9-16
constexpr int NTILES  = 17;            // 136 cols / 8
constexpr int KSTEPS  = 64;            // 1024 / 16, one kstep per pipeline stage
constexpr int KSTEP_U32 = NTILES * 32 * 4;           // 2176 u32 = 8704 B per kstep (B frags)
constexpr int M_CTA   = 64;

// gemm1 pipeline: 3-buffer ring, 1 kstep per stage
constexpr int G1_BST   = 8704;             // B bytes per stage
constexpr int G1_XROWB = 96;               // X smem row stride (2-way conflicts max)
constexpr int G1_XST   = M_CTA * G1_XROWB; // 6144 B per stage
constexpr int G1_STAGE = G1_BST + G1_XST;  // 14848
constexpr int G1_BCH   = G1_BST / 16;      // 544 16B chunks
constexpr int G1_XDATA = M_CTA * 4;        // 256 chunks (4 x 16B per row)
constexpr int G1_CHUNKS = G1_BCH + G1_XDATA;   // 800

// GEMM2 mma tiling: per CTA 128 rows x 128 cols, K=128 (8 ksteps), 16 ntiles
constexpr int G2_NT   = 16;
constexpr int G2_KS   = 8;
constexpr int TFRAG_U32_PER_NT = G2_KS * 32 * 4;         // 1024 u32 per (global) ntile
constexpr int TFRAG_U32 = 64 * TFRAG_U32_PER_NT;         // 65536 u32 = 256 KB total
constexpr int SM2_U32  = G2_NT * TFRAG_U32_PER_NT;       // 16384 u32 = 64 KB per CTA
constexpr int SM2_BYTES = SM2_U32 * 4;

// Scratch (static device globals — no runtime allocation)
// coef in mma A-fragment layout: [rowblock][ks][lane][reg] u32 (2 bf16 per u32)
constexpr size_t COEF_U32 = (size_t)(ROWS_MAX / 16) * 8 * 32 * 4;
__device__ __align__(16) uint32_t g_coef_fh[COEF_U32];
__device__ __align__(16) uint32_t g_coef_fl[COEF_U32];
__device__ float g_CS[F];
__device__ float g_SS[F];
__device__ float g_invS[ROWS_MAX];
// GEMM1 B fragments: [ks][ntile][lane][4] = {bh0,bh1,bl0,bl1}
__device__ __align__(16) uint32_t g_Bfrag[(size_t)KSTEPS * KSTEP_U32];
// GEMM2 B fragments (T table): [nt][ks][lane][4] = {bh0,bh1,bl0,bl1}
__device__ __align__(16) uint32_t g_Tfrag[(size_t)TFRAG_U32];

// ---- helpers ----
__device__ __forceinline__ uint32_t smem_u32(const void* p) {
    uint32_t a;
    asm("{ .reg .u64 t; cvta.to.shared.u64 t, %1; cvt.u32.u64 %0, t; }" : "=r"(a) : "l"(p));
    return a;
}
__device__ __forceinline__ uint32_t pack_hi(float2 v) {
    __nv_bfloat162 h = __floats2bfloat162_rn(v.x, v.y);
    return *(uint32_t*)&h;
}
__device__ __forceinline__ uint32_t pack_lo(float2 v, uint32_t hp) {
    __nv_bfloat162 h = *(__nv_bfloat162*)&hp;
    float rx = v.x - __bfloat162float(h.x);
    float ry = v.y - __bfloat162float(h.y);
    __nv_bfloat162 lo = __floats2bfloat162_rn(rx, ry);
    return *(uint32_t*)&lo;
}
__device__ __forceinline__ void mma_bf16(float* c, uint32_t a0, uint32_t a1,
                                         uint32_t a2, uint32_t a3,
                                         uint32_t b0, uint32_t b1) {
    asm volatile(
        "mma.sync.aligned.m16n8k16.row.col.f32.bf16.bf16.f32 "
        "{%0,%1,%2,%3}, {%4,%5,%6,%7}, {%8,%9}, {%0,%1,%2,%3};"
        : "+f"(c[0]), "+f"(c[1]), "+f"(c[2]), "+f"(c[3])
        : "r"(a0), "r"(a1), "r"(a2), "r"(a3), "r"(b0), "r"(b1));
}
#define CPA16(dst_u32, src_ptr) \
    asm volatile("cp.async.cg.shared.global [%0], [%1], 16;" :: "r"(dst_u32), "l"(src_ptr) : "memory")
#define CPA_COMMIT() asm volatile("cp.async.commit_group;" ::: "memory")
#define CPA_WAIT1()  asm volatile("cp.async.wait_group 1;" ::: "memory")
#define CPA_WAIT0()  asm volatile("cp.async.wait_group 0;" ::: "memory")

// ============================================================
// Kernel 0: column sums of cos/sin table (CS/SS only)
// ============================================================
__global__ void table_kernel() {
    const int f = blockIdx.x;
    const int d = threadIdx.x;
    float center = -1.0f + (2 * d + 1) * (1.0f / 512.0f);
    float arg = center * (float)(f + 1);
    float s, c;
    sincospif(arg, &s, &c);

    __shared__ float sc[512], ss[512];
    sc[d] = c;
    ss[d] = s;
    __syncthreads();
    for (int off = 256; off > 0; off >>= 1) {
        if (d < off) {
            sc[d] += sc[d + off];
            ss[d] += ss[d + off];
        }
        __syncthreads();
    }
    if (d == 0) {
        g_CS[f] = sc[0];
        g_SS[f] = ss[0];
    }
}

// ============================================================
// Kernel 0b: W -> bf16 hi/lo mma B-fragments (GEMM1)
// layout: [ks][nt][lane][4] = {bh0, bh1, bl0, bl1}
// ============================================================
__global__ void wprep_kernel(const float* __restrict__ Wm) {
    const int ks = blockIdx.x;
    const int nt = threadIdx.x >> 5;
    const int lane = threadIdx.x & 31;
    const int n = nt * 8 + (lane >> 2);
    const int kc = ks * 16 + (lane & 3) * 2;
    float2 wa = make_float2(0.f, 0.f), wb = make_float2(0.f, 0.f);
    if (n < N1) {
        const float* wr = Wm + (size_t)n * DIN;
        wa = make_float2(wr[kc], wr[kc + 1]);
        wb = make_float2(wr[kc + 8], wr[kc + 9]);
    }
    uint32_t h0 = pack_hi(wa), h1 = pack_hi(wb);
    uint32_t l0 = pack_lo(wa, h0), l1 = pack_lo(wb, h1);
    size_t idx = (((size_t)ks * NTILES + nt) * 32 + lane) * 4;
    g_Bfrag[idx + 0] = h0;
    g_Bfrag[idx + 1] = h1;
    g_Bfrag[idx + 2] = l0;
    g_Bfrag[idx + 3] = l1;
}

// ============================================================
// Kernel 0c: T table -> bf16 hi/lo mma B-fragments (GEMM2)
// layout: [nt][ks][lane][4] = {bh0, bh1, bl0, bl1}
// ============================================================
__device__ __forceinline__ float tval(int k, float center) {
    float s, c;
    if (k < F) {
        sincospif(center * (float)(k + 1), &s, &c);
        return c;
    } else {
        sincospif(center * (float)(k - F + 1), &s, &c);
        return -s;
    }
}
__global__ void tprep_kernel() {
    const int nt = blockIdx.x;
    const int ks = threadIdx.x >> 5;
    const int lane = threadIdx.x & 31;
    const int n = nt * 8 + (lane >> 2);
    const int kc = ks * 16 + (lane & 3) * 2;
    float center = -1.0f + (2 * n + 1) * (1.0f / 512.0f);
    float2 va = make_float2(tval(kc, center), tval(kc + 1, center));
    float2 vb = make_float2(tval(kc + 8, center), tval(kc + 9, center));
    uint32_t h0 = pack_hi(va), h1 = pack_hi(vb);
    uint32_t l0 = pack_lo(va, h0), l1 = pack_lo(vb, h1);
    size_t idx = (((size_t)nt * G2_KS + ks) * 32 + lane) * 4;
    g_Tfrag[idx + 0] = h0;
    g_Tfrag[idx + 1] = h1;
    g_Tfrag[idx + 2] = l0;
    g_Tfrag[idx + 3] = l1;
}

// ============================================================
// coef fragment-layout writer: element (grow, col), value v ->
// hi/lo bf16 at [rowblock][ks][lane][reg][half]
// ============================================================
__device__ __forceinline__ void write_coef(int grow, int col, float v) {
    int rb = grow >> 4, r = grow & 15;
    int ks = col >> 4, kc = col & 15;
    int lane2 = (r & 7) * 4 + ((kc & 7) >> 1);
    int reg = (r >> 3) | ((kc >> 3) << 1);
    int half = kc & 1;
    size_t uoff = (((size_t)rb * 8 + ks) * 32 + lane2) * 4 + reg;
    __nv_bfloat16 vh = __float2bfloat16(v);
    ((__nv_bfloat16*)g_coef_fh)[uoff * 2 + half] = vh;
    ((__nv_bfloat16*)g_coef_fl)[uoff * 2 + half] =
        __float2bfloat16(v - __bfloat162float(vh));
}

// ============================================================
// Kernel 1 (HMMA, cp.async 3-stage ring, 4 CTAs/SM):
// M=64 rows/CTA; warps 0-3: ntiles 0-8, warps 4-7: ntiles 9-16,
// (w&3) selects 16-row slice. One LDS.128 per (ntile,kstep) B load.
// Epilogue: sliding-window 4-lag autocorr (zero-padded rows).
// ============================================================
constexpr int ZSTR  = 69;                            // complex stride per row (zero-padded)
constexpr int SM_PZ    = 0;                          // 64 x 69 float2 = 35328
constexpr int SM_CONTR = 35328;                      // 64*64 f32 -> 51712
constexpr int SM_INVR  = 51712;                      // 64 f32 -> 51968
constexpr int SM_BIAS  = 51968;                      // 136 f32 -> 52512
constexpr int SM1_BYTES = 52512 + 64;
// ring occupies [0, 44544); overlay used only after mainloop

__global__ void __launch_bounds__(256, 4)
gemm1_mma_kernel(const float* __restrict__ X, const float* __restrict__ bias) {
    extern __shared__ char sm[];
    const uint32_t sb = smem_u32(sm);
    const int tid = threadIdx.x;
    const int w = tid >> 5;
    const int lane = tid & 31;
    const int wg = w >> 2;           // 0: nt 0-8, 1: nt 9-16
    const int wr = w & 3;            // 16-row slice
    const int m0 = blockIdx.x * M_CTA;

    if (tid < 136) ((float*)(sm + SM_BIAS))[tid] = (tid < N1) ? bias[tid] : 0.0f;

    float acc[9][4];
#pragma unroll
    for (int nt = 0; nt < 9; nt++)
#pragma unroll
        for (int i = 0; i < 4; i++) acc[nt][i] = 0.0f;

    const char* gB = (const char*)g_Bfrag;

    // stage copy: B chunk ids [0,544), X chunk ids [544,800)
    auto copy_stage = [&](int s, int buf) {
        const uint32_t dstb = sb + buf * G1_STAGE;
        const char* srcB = gB + (size_t)s * G1_BST;
#pragma unroll
        for (int it = 0; it < 4; it++) {
            int i = tid + 256 * it;
            if (i < G1_BCH) {
                CPA16(dstb + i * 16, srcB + i * 16);
            } else if (i < G1_CHUNKS) {
                int j = i - G1_BCH;
                int row = j >> 2;
                int c4 = j & 3;
                const float* src = X + (size_t)(m0 + row) * DIN + s * 16 + c4 * 4;
                CPA16(dstb + G1_BST + row * G1_XROWB + c4 * 16, src);
            }
        }
    };

    copy_stage(0, 0); CPA_COMMIT();
    copy_stage(1, 1); CPA_COMMIT();

    const int xoff = (wr * 16 + (lane >> 2)) * G1_XROWB + (lane & 3) * 8;

    int cur = 0;                     // buffer of stage s
    for (int s = 0; s < KSTEPS; s++) {
        if (s < KSTEPS - 1) { CPA_WAIT1(); }
        else                { CPA_WAIT0(); }
        __syncthreads();
        if (s + 2 < KSTEPS) {
            int tgt = cur ? cur - 1 : 2;     // (cur + 2) % 3
            copy_stage(s + 2, tgt);
            CPA_COMMIT();
        }

        const char* bb = sm + cur * G1_STAGE;
        const char* xb = bb + G1_BST + xoff;
        float2 v1a = *(const float2*)(xb);
        float2 v1b = *(const float2*)(xb + 32);
        float2 v2a = *(const float2*)(xb + 8 * G1_XROWB);
        float2 v2b = *(const float2*)(xb + 8 * G1_XROWB + 32);
        uint32_t ah0 = pack_hi(v1a), ah1 = pack_hi(v2a);
        uint32_t ah2 = pack_hi(v1b), ah3 = pack_hi(v2b);
        uint32_t al0 = pack_lo(v1a, ah0), al1 = pack_lo(v2a, ah1);
        uint32_t al2 = pack_lo(v1b, ah2), al3 = pack_lo(v2b, ah3);

        const char* kbase = bb + lane * 16;
        if (wg == 0) {
#pragma unroll
            for (int nt = 0; nt < 9; nt++) {
                uint4 f = *(const uint4*)(kbase + nt * 512);
                mma_bf16(acc[nt], ah0, ah1, ah2, ah3, f.x, f.y);
                mma_bf16(acc[nt], ah0, ah1, ah2, ah3, f.z, f.w);
                mma_bf16(acc[nt], al0, al1, al2, al3, f.x, f.y);
            }
        } else {
#pragma unroll
            for (int nt = 0; nt < 8; nt++) {
                uint4 f = *(const uint4*)(kbase + (9 + nt) * 512);
                mma_bf16(acc[nt], ah0, ah1, ah2, ah3, f.x, f.y);
                mma_bf16(acc[nt], ah0, ah1, ah2, ah3, f.z, f.w);
                mma_bf16(acc[nt], al0, al1, al2, al3, f.x, f.y);
            }
        }
        cur = (cur == 2) ? 0 : cur + 1;
    }
    __syncthreads();   // ring dead; overlay pz

    // ---- scatter acc (+bias) into interleaved pz[row][c], zero pad ----
    // c < 65: z.x = p[c];  c >= 65: z[c-65].y = p[c]
    float* pzf = (float*)(sm + SM_PZ);
    float* sbias = (float*)(sm + SM_BIAS);
    // zero the pad region: complex [65..68] per row = floats [130..137]
    for (int i = tid; i < M_CTA * 8; i += 256) {
        int row = i >> 3;
        pzf[row * (2 * ZSTR) + 130 + (i & 7)] = 0.0f;
    }
    {
        const int r1 = wr * 16 + (lane >> 2);
        const int cb = (lane & 3) * 2;
        const int NT_MY = wg ? 8 : 9;
        const int NT0 = wg ? 9 : 0;
#pragma unroll
        for (int nt = 0; nt < 9; nt++) {
            if (nt < NT_MY) {
                int col0 = (NT0 + nt) * 8 + cb;
#pragma unroll
                for (int h = 0; h < 2; h++) {
                    int col = col0 + h;
                    if (col < N1) {
                        float bv = sbias[col];
                        float v0 = acc[nt][h] + bv;       // row r1
                        float v1 = acc[nt][2 + h] + bv;   // row r1+8
                        int ci = (col < L) ? col * 2 : (col - L) * 2 + 1;
                        pzf[r1 * (2 * ZSTR) + ci] = v0;
                        pzf[(r1 + 8) * (2 * ZSTR) + ci] = v1;
                    }
                }
            }
        }
    }
    __syncthreads();

    // ---- autocorrelation: sliding-window, 4 lags per thread ----
    const float2* pz = (const float2*)(sm + SM_PZ);
    float* contrib = (float*)(sm + SM_CONTR);
    float* inv_r0 = (float*)(sm + SM_INVR);

    if (tid < M_CTA) {
        const float2* zr = pz + tid * ZSTR;
        float s = 0.0f;
        for (int j = 0; j < L; j++) {
            float2 u = zr[j];
            s += u.x * u.x + u.y * u.y;
        }
        inv_r0[tid] = 1.0f / s;
    }
    __syncthreads();

    // tasks: (row, lag-group). lane -> row (contiguous rows per warp,
    // identical lag-group per warp => balanced, ~2-way conflicts at stride 69)
#pragma unroll
    for (int it = 0; it < 4; it++) {
        const int row = tid & 63;
        const int lag4 = (tid >> 6) + 4 * it;    // 0..15
        const int lag0 = 1 + 4 * lag4;
        const float2* zr = pz + row * ZSTR;

        float2 w0 = zr[lag0], w1 = zr[lag0 + 1], w2 = zr[lag0 + 2], w3 = zr[lag0 + 3];
        float sr0 = 0.f, si0 = 0.f, sr1 = 0.f, si1 = 0.f;
        float sr2 = 0.f, si2 = 0.f, sr3 = 0.f, si3 = 0.f;
        const int n = L - lag0;
        for (int j = 0; j < n; j++) {
            float2 v = zr[j];
            sr0 += w0.x * v.x + w0.y * v.y;  si0 += w0.y * v.x - w0.x * v.y;
            sr1 += w1.x * v.x + w1.y * v.y;  si1 += w1.y * v.x - w1.x * v.y;
            sr2 += w2.x * v.x + w2.y * v.y;  si2 += w2.y * v.x - w2.x * v.y;
            sr3 += w3.x * v.x + w3.y * v.y;  si3 += w3.y * v.x - w3.x * v.y;
            w0 = w1; w1 = w2; w2 = w3;
            w3 = zr[j + lag0 + 4];
        }
        float ir = inv_r0[row];
        float srs[4] = {sr0, sr1, sr2, sr3};
        float sis[4] = {si0, si1, si2, si3};
#pragma unroll
        for (int i = 0; i < 4; i++) {
            int lag = lag0 + i;
            float cr = srs[i] * ir;
            float ci_ = sis[i] * ir;
            write_coef(m0 + row, lag - 1, cr);
            write_coef(m0 + row, F + lag - 1, ci_);
            contrib[row * 64 + (lag - 1)] = cr * g_CS[lag - 1] - ci_ * g_SS[lag - 1];
        }
    }
    __syncthreads();

    if (tid < M_CTA) {
        const float* cb = contrib + tid * 64;
        float S = 0.5f * (float)D;
        for (int k = 0; k < 64; k++) S += cb[k];
        g_invS[m0 + tid] = 1.0f / S;
    }
}

// ============================================================
// Kernel 2 (HMMA): like = coef @ T (+0.5) -> log epilogue
// A: 2 LDG.128 per warp per ks (coef fragment layout);
// B: 1 LDS.128 per (ntile, ks).
// ============================================================
__global__ void __launch_bounds__(256)
gemm2_mma_kernel(float* __restrict__ out) {
    extern __shared__ char sm[];
    uint32_t* smB = (uint32_t*)sm;
    const int tid = threadIdx.x;
    const int w = tid >> 5;
    const int lane = tid & 31;
    const int m0 = blockIdx.x * 128;
    const int nb = blockIdx.y;

    {
        const uint4* src = (const uint4*)(g_Tfrag + (size_t)nb * SM2_U32);
        uint4* dst = (uint4*)smB;
        for (int i = tid; i < SM2_U32 / 4; i += 256) dst[i] = src[i];
    }
    __syncthreads();

    float acc[G2_NT][4];
#pragma unroll
    for (int nt = 0; nt < G2_NT; nt++)
#pragma unroll
        for (int i = 0; i < 4; i++) acc[nt][i] = 0.0f;

    const int rb = blockIdx.x * 8 + w;     // global 16-row block
    const uint4* cfh = (const uint4*)g_coef_fh + ((size_t)rb * 8) * 32 + lane;
    const uint4* cfl = (const uint4*)g_coef_fl + ((size_t)rb * 8) * 32 + lane;
    const uint4* smB4 = (const uint4*)smB;

#pragma unroll
    for (int ks = 0; ks < G2_KS; ks++) {
        uint4 Ah = cfh[ks * 32];
        uint4 Al = cfl[ks * 32];
#pragma unroll
        for (int nt = 0; nt < G2_NT; nt++) {
            uint4 f = smB4[(nt * G2_KS + ks) * 32 + lane];
            mma_bf16(acc[nt], Ah.x, Ah.y, Ah.z, Ah.w, f.x, f.y);
            mma_bf16(acc[nt], Ah.x, Ah.y, Ah.z, Ah.w, f.z, f.w);
            mma_bf16(acc[nt], Al.x, Al.y, Al.z, Al.w, f.x, f.y);
        }
    }

    const int r1 = m0 + w * 16 + (lane >> 2);
    const int kc0 = (lane & 3) * 2;
    const float is0 = g_invS[r1];
    const float is1 = g_invS[r1 + 8];
    float* o0 = out + (size_t)r1 * D + nb * 128 + kc0;
    float* o1 = o0 + 8 * (size_t)D;
#pragma unroll
    for (int nt = 0; nt < G2_NT; nt++) {
        float2 u0, u1;
        u0.x = __logf(fmaf(acc[nt][0] + 0.5f, is0, 1e-5f));
        u0.y = __logf(fmaf(acc[nt][1] + 0.5f, is0, 1e-5f));
        u1.x = __logf(fmaf(acc[nt][2] + 0.5f, is1, 1e-5f));
        u1.y = __logf(fmaf(acc[nt][3] + 0.5f, is1, 1e-5f));
        *(float2*)(o0 + nt * 8) = u0;
        *(float2*)(o1 + nt * 8) = u1;
    }
}

extern "C" void kernel_launch(void* const* d_in, const int* in_sizes, int n_in,
                              void* d_out, int out_size) {
    const float* X = (const float*)d_in[0];     // batch [16,4096,1024]
    const float* Wm = (const float*)d_in[1];    // W [130,1024]
    const float* bias = (const float*)d_in[2];  // b [130]
    float* out = (float*)d_out;                 // [16,4096,512] f32

    const int rows = in_sizes[0] / DIN;         // 65536

    static bool attr_set = false;
    if (!attr_set) {
        cudaFuncSetAttribute(gemm1_mma_kernel,
                             cudaFuncAttributeMaxDynamicSharedMemorySize, SM1_BYTES);
        cudaFuncSetAttribute(gemm2_mma_kernel,
                             cudaFuncAttributeMaxDynamicSharedMemorySize, SM2_BYTES);
        attr_set = true;
    }

    table_kernel<<<F, D>>>();
    wprep_kernel<<<KSTEPS, NTILES * 32>>>(Wm);
    tprep_kernel<<<64, 256>>>();
    gemm1_mma_kernel<<<rows / M_CTA, 256, SM1_BYTES>>>(X, bias);
    gemm2_mma_kernel<<<dim3(rows / 128, 4), 256, SM2_BYTES>>>(out);
}